// round 12
// baseline (speedup 1.0000x reference)
#include <cuda_runtime.h>
#include <stdint.h>
#include <math.h>

#define NB 128      // batch
#define NT 512      // time steps
#define ND 256      // input dim
#define NH 512      // hidden dim
#define NG 2048     // 4*NH
#define NCTA 128    // persistent grid size (all resident)
#define KC 64       // K-chunk for recurrent GEMM
#define HP 132      // smem pitch (floats) for transposed h chunk; 528B = 33*16B
#define NCHUNK (NH / KC)   // 8
#define NGROUP 8           // CTA groups of 16; group G produces h cols [G*64,(G+1)*64)
#define REP 32             // flag replica stride (uints) = 128B

// packed fp32x2 FMA
#define FMA2(d, a, b) \
    asm("fma.rn.f32x2 %0, %1, %2, %0;" : "+l"(d) : "l"(a), "l"(b))
#define PACK2(out, v) \
    asm("mov.b64 %0, {%1, %1};" : "=l"(out) : "r"(__float_as_uint(v)))

// -------------------- device scratch (no allocs allowed) --------------------
// zx stored TRANSPOSED: g_zx[t][col][b]  (col = gate*512 + hj)
__device__ float g_zx[(size_t)NT * NG * NB];
__device__ float g_hbuf[2][NH * NB];           // transposed hidden state: [hj][b]
// replicated arrival flags: group G, replica R at [(G*8 + R)*REP]
__device__ unsigned g_arrive[NGROUP * 8 * REP];

// -------------------- cp.async helpers --------------------
__device__ __forceinline__ void cpa16(uint32_t dst_smem, const void* src) {
    asm volatile("cp.async.cg.shared.global [%0], [%1], 16;\n"
                 :: "r"(dst_smem), "l"(src));
}
__device__ __forceinline__ void cpa_commit() {
    asm volatile("cp.async.commit_group;\n");
}
__device__ __forceinline__ void cpa_wait0() {
    asm volatile("cp.async.wait_group 0;\n");
}

// -------------------- flag ops --------------------
__device__ __forceinline__ void wait_ge(const unsigned* p, unsigned target) {
    unsigned v;
    asm volatile("ld.acquire.gpu.global.u32 %0, [%1];" : "=r"(v) : "l"(p));
    while (v < target) {
        __nanosleep(64);
        asm volatile("ld.acquire.gpu.global.u32 %0, [%1];" : "=r"(v) : "l"(p));
    }
}
__device__ __forceinline__ void red_release(unsigned* p, unsigned v) {
    asm volatile("red.release.gpu.global.add.u32 [%0], %1;" :: "l"(p), "r"(v));
}

// -------------------- fast activations (budget: rel_err < 1e-3) ------------
__device__ __forceinline__ float fsigmoid(float x) {
    return 1.f / (1.f + __expf(-x));
}
__device__ __forceinline__ float ftanh(float x) {
    return 1.f - 2.f / (1.f + __expf(2.f * x));
}

// -------------------- Phase 1: zx_t[t][col][b] = (x@Wx + b) transposed ------
// Block (0,0) also resets the flag words (visible to lstm via stream order).
__global__ void __launch_bounds__(256) zx_gemm(const float* __restrict__ x,
                                               const float* __restrict__ Wx,
                                               const float* __restrict__ bias) {
    __shared__ float shAT[16 * HP];   // [kk][b] transposed A tile
    __shared__ float shB[16 * 64];    // [kk][j]

    const int nt = blockIdx.x;        // 0..31
    const int mt = blockIdx.y;        // 0..511  (== t, tile M = 128 = NB)
    const int tid = threadIdx.x;
    const int c0 = (tid & 15) << 2;
    const int r0 = (tid >> 4) << 3;

    if (nt == 0 && mt == 0) {         // reset sync flags for this replay
        for (int i = tid; i < NGROUP * 8 * REP; i += 256) g_arrive[i] = 0u;
    }

    unsigned long long acc2[4][4];    // [row-pair][col], packed fp32x2
#pragma unroll
    for (int p = 0; p < 4; ++p)
#pragma unroll
        for (int c = 0; c < 4; ++c) acc2[p][c] = 0ull;

    for (int k0 = 0; k0 < ND; k0 += 16) {
#pragma unroll
        for (int i = 0; i < 8; ++i) {
            int flat = i * 256 + tid;
            int kk = flat & 15;
            int b = flat >> 4;
            shAT[kk * HP + b] = x[(size_t)b * (NT * ND) + (size_t)mt * ND + k0 + kk];
        }
#pragma unroll
        for (int i = 0; i < 4; ++i) {
            int flat = i * 256 + tid;
            int j = flat & 63;
            int kk = flat >> 6;
            shB[kk * 64 + j] = Wx[(size_t)(k0 + kk) * NG + nt * 64 + j];
        }
        __syncthreads();
#pragma unroll
        for (int kk = 0; kk < 16; ++kk) {
            const float4 b4 = *(const float4*)&shB[kk * 64 + c0];
            unsigned long long bd[4];
            PACK2(bd[0], b4.x); PACK2(bd[1], b4.y);
            PACK2(bd[2], b4.z); PACK2(bd[3], b4.w);
            const ulonglong2 a01 = *(const ulonglong2*)&shAT[kk * HP + r0];
            const ulonglong2 a23 = *(const ulonglong2*)&shAT[kk * HP + r0 + 4];
            const unsigned long long ap[4] = {a01.x, a01.y, a23.x, a23.y};
#pragma unroll
            for (int p = 0; p < 4; ++p)
#pragma unroll
                for (int c = 0; c < 4; ++c) FMA2(acc2[p][c], ap[p], bd[c]);
        }
        __syncthreads();
    }

#pragma unroll
    for (int c = 0; c < 4; ++c) {
        const float bc = bias[nt * 64 + c0 + c];
        float a[8];
#pragma unroll
        for (int p = 0; p < 4; ++p) {
            a[2 * p]     = __uint_as_float((unsigned)(acc2[p][c] & 0xFFFFFFFFull)) + bc;
            a[2 * p + 1] = __uint_as_float((unsigned)(acc2[p][c] >> 32)) + bc;
        }
        size_t base = ((size_t)mt * NG + nt * 64 + c0 + c) * NB + r0;
        *(float4*)&g_zx[base]     = make_float4(a[0], a[1], a[2], a[3]);
        *(float4*)&g_zx[base + 4] = make_float4(a[4], a[5], a[6], a[7]);
    }
}

// -------------------- Phase 2: persistent recurrent kernel (512 thr) --------
// CTA g owns h-columns [4g, 4g+4) and z-columns {gate*512 + 4g + w}.
// 16 warps (4/SMSP) for latency hiding. Each thread: 4 batch rows x 1 z-col
// in the GEMM (2 packed accumulators), 1 cell in the gate stage.
__global__ void __launch_bounds__(512, 1) lstm_persistent(
    const float* __restrict__ Wh, float* __restrict__ out) {
    extern __shared__ float smem[];
    float* sh_wh2 = smem;                              // [512][16] float2
    float* sh_h   = smem + NH * 16 * 2;                // [2][KC][HP]
    float* sh_z   = smem + NH * 16 * 2 + 2 * KC * HP;  // [128][16]

    const int g = blockIdx.x;    // 0..127
    const int tid = threadIdx.x;
    const int grp = g >> 4;      // own producer group (= consumer replica id)

    // Wh slice, duplicated into both lanes of a float2
    for (int i = tid; i < NH * 16; i += 512) {
        int k = i >> 4, c = i & 15;
        int gcol = ((c >> 2) << 9) + (g << 2) + (c & 3);  // gate*512 + 4g + w
        float wv = Wh[(size_t)k * NG + gcol];
        ((float2*)sh_wh2)[i] = make_float2(wv, wv);
    }

    const int col = tid & 15;                 // local z-column
    const int rb  = (tid >> 4) << 2;          // 4 batch rows: rb..rb+3
    const int gcol = ((col >> 2) << 9) + (g << 2) + (col & 3);
    const int gb = tid >> 2;                  // gate-stage batch row (0..127)
    const int gw = tid & 3;                   // gate-local h-column
    const int hj = (g << 2) + gw;             // global h-column owned
    float cst = 0.f;                          // 1 cell per thread

    // cp.async mapping: 2048 16B-segments per chunk, 4 per thread
    uint32_t cp_dst[4];
    int      cp_src[4];
    {
        uint32_t sh_h_base = (uint32_t)__cvta_generic_to_shared(sh_h);
#pragma unroll
        for (int i = 0; i < 4; ++i) {
            int s = i * 512 + tid;
            int kk = s >> 5;
            int b4 = (s & 31) << 2;
            cp_dst[i] = sh_h_base + (uint32_t)(kk * HP + b4) * 4u;
            cp_src[i] = kk * NB + b4;
        }
    }
    const uint32_t buf_bytes = (uint32_t)(KC * HP) * 4u;

    __syncthreads();

    for (int t = 0; t < NT; ++t) {
        // ---- coalesced zx prefetch (hidden behind GEMM) ----
        const float4 z0 = __ldg((const float4*)(g_zx + ((size_t)t * NG + gcol) * NB + rb));

        unsigned long long acc2[2] = {0ull, 0ull};     // 4 rows packed

        if (t > 0) {
            const float* hbuf = g_hbuf[(t + 1) & 1];   // written at t-1
            const unsigned tgt = 16u * (unsigned)t;

            // prologue: own group first; tid0 polls replica grp, barrier spreads
            if (tid == 0) wait_ge(&g_arrive[(grp * 8 + grp) * REP], tgt);
            __syncthreads();
#pragma unroll
            for (int i = 0; i < 4; ++i)
                cpa16(cp_dst[i], hbuf + grp * (KC * NB) + cp_src[i]);
            cpa_commit();

            for (int i = 0; i < NCHUNK; ++i) {
                int cur = grp + i; if (cur >= NCHUNK) cur -= NCHUNK;
                int nx = cur + 1; if (nx >= NCHUNK) nx -= NCHUNK;
                cpa_wait0();             // chunk cur resident (this thread)
                if (i < NCHUNK - 1 && tid == 0)
                    wait_ge(&g_arrive[(nx * 8 + grp) * REP], tgt);
                __syncthreads();         // chunk ready + flag ok + prev compute done
                if (i < NCHUNK - 1) {
                    const float* src = hbuf + nx * (KC * NB);
                    uint32_t dofs = ((i + 1) & 1) ? buf_bytes : 0u;
#pragma unroll
                    for (int j = 0; j < 4; ++j)
                        cpa16(cp_dst[j] + dofs, src + cp_src[j]);
                    cpa_commit();
                }
                const float* hb = sh_h + ((i & 1) ? KC * HP : 0);
                const double* whk = (const double*)sh_wh2 + cur * KC * 16;
#pragma unroll 8
                for (int kk = 0; kk < KC; ++kk) {
                    const unsigned long long w2 =
                        *(const unsigned long long*)&whk[kk * 16 + col];
                    const ulonglong2 h4 = *(const ulonglong2*)&hb[kk * HP + rb];
                    FMA2(acc2[0], h4.x, w2);
                    FMA2(acc2[1], h4.y, w2);
                }
            }
        }

        // z = h@Wh + zx  -> smem (unpack packed accumulators)
        {
            float a0 = __uint_as_float((unsigned)(acc2[0] & 0xFFFFFFFFull));
            float a1 = __uint_as_float((unsigned)(acc2[0] >> 32));
            float a2 = __uint_as_float((unsigned)(acc2[1] & 0xFFFFFFFFull));
            float a3 = __uint_as_float((unsigned)(acc2[1] >> 32));
            sh_z[(rb + 0) * 16 + col] = a0 + z0.x;
            sh_z[(rb + 1) * 16 + col] = a1 + z0.y;
            sh_z[(rb + 2) * 16 + col] = a2 + z0.z;
            sh_z[(rb + 3) * 16 + col] = a3 + z0.w;
        }
        __syncthreads();

        // gates: 1 cell per thread (row gb, column hj)
        {
            float zi = sh_z[gb * 16 + 0 + gw];
            float zf = sh_z[gb * 16 + 4 + gw];
            float zg = sh_z[gb * 16 + 8 + gw];
            float zo = sh_z[gb * 16 + 12 + gw];
            float si = fsigmoid(zi);
            float sf = fsigmoid(zf);
            float tg = ftanh(zg);
            float so = fsigmoid(zo);
            float cn = sf * cst + si * tg;
            cst = cn;
            float hn = so * ftanh(cn);
            __stcg(&g_hbuf[t & 1][hj * NB + gb], hn);               // transposed h
            out[(size_t)gb * NT * NH + (size_t)t * NH + hj] = hn;   // outputs[b][t][hj]
            if (t == NT - 1) {
                out[(size_t)NB * NT * NH + (size_t)gb * NH + hj] = hn;               // hT
                out[(size_t)NB * NT * NH + (size_t)NB * NH + (size_t)gb * NH + hj] = cn; // cT
            }
        }

        // publish: syncthreads (CTA h-stores ordered) + cumulative release adds
        __syncthreads();
        if (tid < 8) red_release(&g_arrive[(grp * 8 + tid) * REP], 1u);
    }
}

// -------------------- launch --------------------
extern "C" void kernel_launch(void* const* d_in, const int* in_sizes, int n_in,
                              void* d_out, int out_size) {
    const float* x    = (const float*)d_in[0];  // [B,T,D]
    const float* Wx   = (const float*)d_in[1];  // [D,4H]
    const float* Wh   = (const float*)d_in[2];  // [H,4H]
    const float* bias = (const float*)d_in[3];  // [4H]
    float* out = (float*)d_out;

    dim3 g1(NG / 64, (NT * NB) / 128);          // (32, 512)
    zx_gemm<<<g1, 256>>>(x, Wx, bias);

    const int smem_bytes = (NH * 16 * 2 + 2 * KC * HP + NB * 16) * (int)sizeof(float); // 141312
    cudaFuncSetAttribute(lstm_persistent,
                         cudaFuncAttributeMaxDynamicSharedMemorySize, smem_bytes);
    lstm_persistent<<<NCTA, 512, smem_bytes>>>(Wh, out);
}

// round 14
// speedup vs baseline: 1.6837x; 1.6837x over previous
#include <cuda_runtime.h>
#include <stdint.h>
#include <math.h>

#define NB 128      // batch
#define NT 512      // time steps
#define ND 256      // input dim
#define NH 512      // hidden dim
#define NG 2048     // 4*NH
#define NCTA 128    // persistent grid size (all resident)
#define KC 64       // K-chunk (hj) per pipeline stage
#define HP 132      // smem pitch (floats) for h chunk; 528B, 16B-aligned
#define NCHUNK (NH / KC)   // 8
#define NGROUP 8           // CTA groups of 16; group G produces h cols [G*64,(G+1)*64)
#define REP 32             // flag replica stride (uints) = 128B

// packed fp32x2 FMA
#define FMA2(d, a, b) \
    asm("fma.rn.f32x2 %0, %1, %2, %0;" : "+l"(d) : "l"(a), "l"(b))
#define PACK2(out, v) \
    asm("mov.b64 %0, {%1, %1};" : "=l"(out) : "r"(__float_as_uint(v)))
#define LO(u) __uint_as_float((unsigned)((u) & 0xFFFFFFFFull))
#define HI(u) __uint_as_float((unsigned)((u) >> 32))

// -------------------- device scratch (no allocs allowed) --------------------
__device__ float g_zx[(size_t)NT * NB * NG];   // NATURAL layout [t][b][col]
__device__ float g_hbuf[2][NH * NB];           // transposed hidden state: [hj][b]
// replicated arrival flags: group G, replica R at [(G*8 + R)*REP]
__device__ unsigned g_arrive[NGROUP * 8 * REP];

// -------------------- cp.async helpers --------------------
__device__ __forceinline__ void cpa16(uint32_t dst_smem, const void* src) {
    asm volatile("cp.async.cg.shared.global [%0], [%1], 16;\n"
                 :: "r"(dst_smem), "l"(src));
}
__device__ __forceinline__ void cpa_commit() {
    asm volatile("cp.async.commit_group;\n");
}
__device__ __forceinline__ void cpa_wait0() {
    asm volatile("cp.async.wait_group 0;\n");
}

// -------------------- flag ops --------------------
__device__ __forceinline__ void wait_ge(const unsigned* p, unsigned target) {
    unsigned v;
    asm volatile("ld.acquire.gpu.global.u32 %0, [%1];" : "=r"(v) : "l"(p));
    while (v < target) {
        __nanosleep(64);
        asm volatile("ld.acquire.gpu.global.u32 %0, [%1];" : "=r"(v) : "l"(p));
    }
}
__device__ __forceinline__ void red_release(unsigned* p, unsigned v) {
    asm volatile("red.release.gpu.global.add.u32 [%0], %1;" :: "l"(p), "r"(v));
}

// -------------------- fast activations (budget: rel_err < 1e-3) ------------
__device__ __forceinline__ float fsigmoid(float x) {
    return 1.f / (1.f + __expf(-x));
}
__device__ __forceinline__ float ftanh(float x) {
    return 1.f - 2.f / (1.f + __expf(2.f * x));
}

// -------------------- Phase 1: zx[t][b][col] = x@Wx + bias ------------------
// Block (0,0) also resets the flag words (visible to lstm via stream order).
__global__ void __launch_bounds__(256) zx_gemm(const float* __restrict__ x,
                                               const float* __restrict__ Wx,
                                               const float* __restrict__ bias) {
    __shared__ float shAT[16 * HP];   // [kk][b] transposed A tile
    __shared__ float shB[16 * 64];    // [kk][j]

    const int nt = blockIdx.x;        // 0..31
    const int mt = blockIdx.y;        // 0..511  (== t, tile M = 128 = NB)
    const int tid = threadIdx.x;
    const int c0 = (tid & 15) << 2;
    const int r0 = (tid >> 4) << 3;

    if (nt == 0 && mt == 0) {         // reset sync flags for this replay
        for (int i = tid; i < NGROUP * 8 * REP; i += 256) g_arrive[i] = 0u;
    }

    unsigned long long acc2[4][4];    // [row-pair][col], packed fp32x2
#pragma unroll
    for (int p = 0; p < 4; ++p)
#pragma unroll
        for (int c = 0; c < 4; ++c) acc2[p][c] = 0ull;

    for (int k0 = 0; k0 < ND; k0 += 16) {
#pragma unroll
        for (int i = 0; i < 8; ++i) {
            int flat = i * 256 + tid;
            int kk = flat & 15;
            int b = flat >> 4;
            shAT[kk * HP + b] = x[(size_t)b * (NT * ND) + (size_t)mt * ND + k0 + kk];
        }
#pragma unroll
        for (int i = 0; i < 4; ++i) {
            int flat = i * 256 + tid;
            int j = flat & 63;
            int kk = flat >> 6;
            shB[kk * 64 + j] = Wx[(size_t)(k0 + kk) * NG + nt * 64 + j];
        }
        __syncthreads();
#pragma unroll
        for (int kk = 0; kk < 16; ++kk) {
            const float4 b4 = *(const float4*)&shB[kk * 64 + c0];
            unsigned long long bd[4];
            PACK2(bd[0], b4.x); PACK2(bd[1], b4.y);
            PACK2(bd[2], b4.z); PACK2(bd[3], b4.w);
            const ulonglong2 a01 = *(const ulonglong2*)&shAT[kk * HP + r0];
            const ulonglong2 a23 = *(const ulonglong2*)&shAT[kk * HP + r0 + 4];
            const unsigned long long ap[4] = {a01.x, a01.y, a23.x, a23.y};
#pragma unroll
            for (int p = 0; p < 4; ++p)
#pragma unroll
                for (int c = 0; c < 4; ++c) FMA2(acc2[p][c], ap[p], bd[c]);
        }
        __syncthreads();
    }

    // store natural layout: g_zx[(mt*NB + r)*NG + nt*64 + c0..c0+3]
    const float4 bb = *(const float4*)&bias[nt * 64 + c0];
#pragma unroll
    for (int p = 0; p < 4; ++p) {
        size_t mlo = (size_t)mt * NB + r0 + 2 * p;
        float4 lo = make_float4(LO(acc2[p][0]) + bb.x, LO(acc2[p][1]) + bb.y,
                                LO(acc2[p][2]) + bb.z, LO(acc2[p][3]) + bb.w);
        float4 hi = make_float4(HI(acc2[p][0]) + bb.x, HI(acc2[p][1]) + bb.y,
                                HI(acc2[p][2]) + bb.z, HI(acc2[p][3]) + bb.w);
        *(float4*)&g_zx[mlo * NG + nt * 64 + c0]       = lo;
        *(float4*)&g_zx[(mlo + 1) * NG + nt * 64 + c0] = hi;
    }
}

// -------------------- Phase 2: persistent recurrent kernel ------------------
// CTA g owns h-columns [4g, 4g+4) -> 16 z-columns (4 gates x 4).
// GEMM: 256 threads = 4 k-quarters x 64 tiles of 8 rows x 4 cols.
// Per kk per thread: 3x LDS.128 (12 phases) for 32 FMA -> 12288 crossbar
// cyc/SM/step vs 40960 before. Split-K partials reduced via smem per step.
__global__ void __launch_bounds__(256, 1) lstm_persistent(
    const float* __restrict__ Wh, float* __restrict__ out) {
    extern __shared__ float smem[];
    float* sh_wh = smem;              // [512][16]          = 8192 floats
    float* sh_h  = smem + 8192;       // [2][KC][HP]        = 16896 floats
    float* sh_p  = smem + 25088;      // [4][128][16]       = 8192 floats
    float* sh_z  = smem + 33280;      // [128][16]          = 2048 floats

    const int g = blockIdx.x;    // 0..127
    const int tid = threadIdx.x;
    const int grp = g >> 4;      // own producer group (= consumer replica id)

    // Wh slice: sh_wh[k][c], c = gate*4 + w  -> global col gate*512 + 4g + w
    for (int i = tid; i < NH * 16; i += 256) {
        int k = i >> 4, c = i & 15;
        int gcol = ((c >> 2) << 9) + (g << 2) + (c & 3);
        sh_wh[i] = Wh[(size_t)k * NG + gcol];
    }

    // ---- GEMM mapping: k-quarter x (16 row-blocks x 4 col-blocks) ----
    const int kq = tid >> 6;          // kk in [kq*16, kq*16+16) of each chunk
    const int x  = tid & 63;
    const int rb = (x >> 2) << 3;     // 8 batch rows
    const int cb = (x & 3) << 2;      // 4 z-cols

    // ---- reduction / zx mapping: thread -> (batch zb, 8 cols zc..zc+7) ----
    const int zb = tid >> 1;
    const int zc = (tid & 1) << 3;    // 0 or 8 (gates {0,1} or {2,3})
    const int zgate0 = zc >> 2;       // 0 or 2

    // ---- gate mapping: 2 cells per thread ----
    const int gw = tid & 3;
    const int gb0 = tid >> 2;         // + u*64
    const int hj = (g << 2) + gw;
    float cst[2] = {0.f, 0.f};

    // cp.async mapping: 2048 16B-segments per chunk, 8 per thread
    uint32_t cp_dst[8];
    int      cp_src[8];
    {
        uint32_t sh_h_base = (uint32_t)__cvta_generic_to_shared(sh_h);
#pragma unroll
        for (int i = 0; i < 8; ++i) {
            int s = i * 256 + tid;
            int kk = s >> 5;
            int b4 = (s & 31) << 2;
            cp_dst[i] = sh_h_base + (uint32_t)(kk * HP + b4) * 4u;
            cp_src[i] = kk * NB + b4;
        }
    }
    const uint32_t buf_bytes = (uint32_t)(KC * HP) * 4u;

    __syncthreads();

    for (int t = 0; t < NT; ++t) {
        // ---- zx prefetch (natural layout, 2x LDG.128, hidden behind GEMM) --
        const float* zrow = g_zx + ((size_t)t * NB + zb) * NG + (g << 2);
        const float4 zxa = __ldg((const float4*)(zrow + (size_t)zgate0 * 512));
        const float4 zxb = __ldg((const float4*)(zrow + (size_t)(zgate0 + 1) * 512));

        unsigned long long acc2[4][4];     // [row-pair][col]
#pragma unroll
        for (int p = 0; p < 4; ++p)
#pragma unroll
            for (int c = 0; c < 4; ++c) acc2[p][c] = 0ull;

        if (t > 0) {
            const float* hbuf = g_hbuf[(t + 1) & 1];   // written at t-1
            const unsigned tgt = 16u * (unsigned)t;

            // prologue: own group first; tid0 polls replica grp, barrier spreads
            if (tid == 0) wait_ge(&g_arrive[(grp * 8 + grp) * REP], tgt);
            __syncthreads();
#pragma unroll
            for (int i = 0; i < 8; ++i)
                cpa16(cp_dst[i], hbuf + grp * (KC * NB) + cp_src[i]);
            cpa_commit();

            for (int i = 0; i < NCHUNK; ++i) {
                int cur = grp + i; if (cur >= NCHUNK) cur -= NCHUNK;
                int nx = cur + 1; if (nx >= NCHUNK) nx -= NCHUNK;
                cpa_wait0();             // chunk cur resident (this thread)
                if (i < NCHUNK - 1 && tid == 0)
                    wait_ge(&g_arrive[(nx * 8 + grp) * REP], tgt);
                __syncthreads();         // chunk ready + flag ok + prev compute done
                if (i < NCHUNK - 1) {
                    const float* src = hbuf + nx * (KC * NB);
                    uint32_t dofs = ((i + 1) & 1) ? buf_bytes : 0u;
#pragma unroll
                    for (int j = 0; j < 8; ++j)
                        cpa16(cp_dst[j] + dofs, src + cp_src[j]);
                    cpa_commit();
                }
                const float* hb  = sh_h + ((i & 1) ? KC * HP : 0);
                const float* whk = sh_wh + cur * (KC * 16) + kq * (16 * 16);
                const float* hbq = hb + kq * (16 * HP);
#pragma unroll
                for (int kk = 0; kk < 16; ++kk) {
                    const ulonglong2 hA = *(const ulonglong2*)&hbq[kk * HP + rb];
                    const ulonglong2 hB = *(const ulonglong2*)&hbq[kk * HP + rb + 4];
                    const float4 wv = *(const float4*)&whk[kk * 16 + cb];
                    unsigned long long w2[4];
                    PACK2(w2[0], wv.x); PACK2(w2[1], wv.y);
                    PACK2(w2[2], wv.z); PACK2(w2[3], wv.w);
#pragma unroll
                    for (int c = 0; c < 4; ++c) {
                        FMA2(acc2[0][c], hA.x, w2[c]);
                        FMA2(acc2[1][c], hA.y, w2[c]);
                        FMA2(acc2[2][c], hB.x, w2[c]);
                        FMA2(acc2[3][c], hB.y, w2[c]);
                    }
                }
            }

            // ---- store split-K partials: sh_p[kq][row][col] ----
#pragma unroll
            for (int p = 0; p < 4; ++p) {
                int rlo = rb + 2 * p;
                float4 lo = make_float4(LO(acc2[p][0]), LO(acc2[p][1]),
                                        LO(acc2[p][2]), LO(acc2[p][3]));
                float4 hi = make_float4(HI(acc2[p][0]), HI(acc2[p][1]),
                                        HI(acc2[p][2]), HI(acc2[p][3]));
                *(float4*)&sh_p[(kq * 128 + rlo) * 16 + cb]       = lo;
                *(float4*)&sh_p[(kq * 128 + rlo + 1) * 16 + cb]   = hi;
            }
            __syncthreads();
        }

        // ---- reduce partials + zx -> sh_z[zb][zc..zc+7] ----
        {
            float4 s0, s1;
            if (t > 0) {
                s0 = *(const float4*)&sh_p[(0 * 128 + zb) * 16 + zc];
                s1 = *(const float4*)&sh_p[(0 * 128 + zb) * 16 + zc + 4];
#pragma unroll
                for (int q = 1; q < 4; ++q) {
                    const float4 a = *(const float4*)&sh_p[(q * 128 + zb) * 16 + zc];
                    const float4 b = *(const float4*)&sh_p[(q * 128 + zb) * 16 + zc + 4];
                    s0.x += a.x; s0.y += a.y; s0.z += a.z; s0.w += a.w;
                    s1.x += b.x; s1.y += b.y; s1.z += b.z; s1.w += b.w;
                }
            } else {
                s0 = make_float4(0.f, 0.f, 0.f, 0.f);
                s1 = s0;
            }
            s0.x += zxa.x; s0.y += zxa.y; s0.z += zxa.z; s0.w += zxa.w;
            s1.x += zxb.x; s1.y += zxb.y; s1.z += zxb.z; s1.w += zxb.w;
            *(float4*)&sh_z[zb * 16 + zc]     = s0;
            *(float4*)&sh_z[zb * 16 + zc + 4] = s1;
        }
        __syncthreads();

        // ---- gates: 2 cells per thread ----
#pragma unroll
        for (int u = 0; u < 2; ++u) {
            int b = gb0 + u * 64;
            float zi = sh_z[b * 16 + 0 + gw];
            float zf = sh_z[b * 16 + 4 + gw];
            float zg = sh_z[b * 16 + 8 + gw];
            float zo = sh_z[b * 16 + 12 + gw];
            float si = fsigmoid(zi);
            float sf = fsigmoid(zf);
            float tg = ftanh(zg);
            float so = fsigmoid(zo);
            float cn = sf * cst[u] + si * tg;
            cst[u] = cn;
            float hn = so * ftanh(cn);
            __stcg(&g_hbuf[t & 1][hj * NB + b], hn);               // transposed h
            out[(size_t)b * NT * NH + (size_t)t * NH + hj] = hn;   // outputs[b][t][hj]
            if (t == NT - 1) {
                out[(size_t)NB * NT * NH + (size_t)b * NH + hj] = hn;               // hT
                out[(size_t)NB * NT * NH + (size_t)NB * NH + (size_t)b * NH + hj] = cn; // cT
            }
        }

        // publish: syncthreads (CTA h-stores ordered) + cumulative release adds
        __syncthreads();
        if (tid < 8) red_release(&g_arrive[(grp * 8 + tid) * REP], 1u);
    }
}

// -------------------- launch --------------------
extern "C" void kernel_launch(void* const* d_in, const int* in_sizes, int n_in,
                              void* d_out, int out_size) {
    const float* x    = (const float*)d_in[0];  // [B,T,D]
    const float* Wx   = (const float*)d_in[1];  // [D,4H]
    const float* Wh   = (const float*)d_in[2];  // [H,4H]
    const float* bias = (const float*)d_in[3];  // [4H]
    float* out = (float*)d_out;

    dim3 g1(NG / 64, (NT * NB) / 128);          // (32, 512)
    zx_gemm<<<g1, 256>>>(x, Wx, bias);

    const int smem_bytes = (8192 + 16896 + 8192 + 2048) * (int)sizeof(float); // 141312
    cudaFuncSetAttribute(lstm_persistent,
                         cudaFuncAttributeMaxDynamicSharedMemorySize, smem_bytes);
    lstm_persistent<<<NCTA, 256, smem_bytes>>>(Wh, out);
}